// round 10
// baseline (speedup 1.0000x reference)
#include <cuda_runtime.h>
#include <cuda_fp16.h>
#include <cstdint>

// Problem constants (fixed by reference)
#define BWIN   2048
#define NTOK   49
#define CDIM   384
#define HHEADS 12
#define DH     32
#define NWMASK 64
#define THREEC 1152
#define MROWS  (BWIN * NTOK)   // 100352

// Scratch (allocation-free rule: __device__ globals)
__device__ __half g_qkvh[(size_t)MROWS * THREEC];   // qkv, fp16
__device__ __half g_xh  [(size_t)MROWS * CDIM];     // x, fp16
__device__ __half g_atth[(size_t)MROWS * CDIM];     // attention out, fp16
__device__ __half g_wqh [(size_t)THREEC * CDIM];    // qkv_w, fp16
__device__ __half g_wph [(size_t)CDIM * CDIM];      // proj_w, fp16

// ---------------------------------------------------------------------------
// helpers
// ---------------------------------------------------------------------------
__device__ __forceinline__ void mma_f16_k16(float c[4],
                                            uint32_t a0, uint32_t a1, uint32_t a2, uint32_t a3,
                                            uint32_t b0, uint32_t b1) {
    asm volatile(
        "mma.sync.aligned.m16n8k16.row.col.f32.f16.f16.f32 "
        "{%0,%1,%2,%3}, {%4,%5,%6,%7}, {%8,%9}, {%0,%1,%2,%3};"
        : "+f"(c[0]), "+f"(c[1]), "+f"(c[2]), "+f"(c[3])
        : "r"(a0), "r"(a1), "r"(a2), "r"(a3), "r"(b0), "r"(b1));
}

__device__ __forceinline__ void mma_f16_k8(float c[4],
                                           uint32_t a0, uint32_t a1, uint32_t b0) {
    asm volatile(
        "mma.sync.aligned.m16n8k8.row.col.f32.f16.f16.f32 "
        "{%0,%1,%2,%3}, {%4,%5}, {%6}, {%0,%1,%2,%3};"
        : "+f"(c[0]), "+f"(c[1]), "+f"(c[2]), "+f"(c[3])
        : "r"(a0), "r"(a1), "r"(b0));
}

__device__ __forceinline__ void ldsm4(uint32_t& r0, uint32_t& r1,
                                      uint32_t& r2, uint32_t& r3, uint32_t addr) {
    asm volatile("ldmatrix.sync.aligned.m8n8.x4.shared.b16 {%0,%1,%2,%3}, [%4];"
                 : "=r"(r0), "=r"(r1), "=r"(r2), "=r"(r3) : "r"(addr));
}

__device__ __forceinline__ uint32_t smem_u32(const void* p) {
    return (uint32_t)__cvta_generic_to_shared(p);
}

// ---------------------------------------------------------------------------
// prepass: fp32 -> fp16 (rn); 8 floats per thread
// ---------------------------------------------------------------------------
__global__ void to_half_kernel(const float* __restrict__ in,
                               __half* __restrict__ out, int n8)
{
    const int i = blockIdx.x * blockDim.x + threadIdx.x;
    if (i < n8) {
        const float4 v0 = ((const float4*)in)[2 * i];
        const float4 v1 = ((const float4*)in)[2 * i + 1];
        __half2 h[4];
        h[0] = __floats2half2_rn(v0.x, v0.y);
        h[1] = __floats2half2_rn(v0.z, v0.w);
        h[2] = __floats2half2_rn(v1.x, v1.y);
        h[3] = __floats2half2_rn(v1.z, v1.w);
        ((uint4*)out)[i] = *(uint4*)h;
    }
}

// ---------------------------------------------------------------------------
// fp16 tensor-core GEMM v6:  C = A @ W^T + bias, fp32 accum
// CTA = 128 threads (4 warps, 2m x 2n), tile 128x128, warp tile 64x64
// (v4's 1:1 LDS:MMA ratio), double-buffered BK=32, 2 CTAs/SM.
// Fragment-permuted smem (dense, 2048 words/buffer each):
//   A word idx: ((kks*8  + mi)*4 + (hi+2ph))*32 + g2*4 + t
//   B word idx: ((kks*16 + ni)*2 + ph)*32 + gb*4 + t
// Producer: each thread owns one row of A and one row of B, 4 chunks each
// (full BK=32), 8x LDG.128 + 8x STS.128 per iter.
// ---------------------------------------------------------------------------
template <typename TO>
__global__ __launch_bounds__(128, 2) void gemm_f16_v6(
    const __half* __restrict__ A,
    const __half* __restrict__ W,
    const float* __restrict__ bias,
    TO* __restrict__ C,
    int Nout, int K)
{
    __shared__ __align__(16) uint32_t As[2][2048];  // 8KB x2
    __shared__ __align__(16) uint32_t Bs[2][2048];  // 8KB x2

    const int tid  = threadIdx.x;
    const int bm   = blockIdx.y * 128;
    const int bn   = blockIdx.x * 128;
    const int lane = tid & 31;
    const int warp = tid >> 5;
    const int warp_m = warp >> 1;    // 0..1 (64-row slab)
    const int warp_n = warp & 1;     // 0..1 (64-col slab)
    const int g = lane >> 2;
    const int t = lane & 3;

    // producer: thread owns row tid of both A and B tiles, 4 chunks (8 halfs)
    const int ldr = tid;

    const __half* Ab = A + (size_t)(bm + ldr) * K;
    const __half* Wb = W + (size_t)(bn + ldr) * K;

    int aoff[4], boff[4];
    {
        const int mi = ldr >> 4;
        const int lr = ldr & 15;
        const int g2 = lr & 7;
        const int hi = lr >> 3;
        const int ni = ldr >> 3;
        const int gb = ldr & 7;
#pragma unroll
        for (int ch = 0; ch < 4; ++ch) {
            const int kks = ch >> 1;
            const int ph  = ch & 1;
            aoff[ch] = ((kks * 8 + mi) * 4 + (hi + 2 * ph)) * 32 + g2 * 4;
            boff[ch] = ((kks * 16 + ni) * 2 + ph) * 32 + gb * 4;
        }
    }

    uint4 ar[4], wr[4];

    auto load_g = [&](int k0) {
#pragma unroll
        for (int ch = 0; ch < 4; ++ch) {
            ar[ch] = *(const uint4*)(Ab + k0 + ch * 8);
            wr[ch] = *(const uint4*)(Wb + k0 + ch * 8);
        }
    };
    auto stash = [&](int bf) {
#pragma unroll
        for (int ch = 0; ch < 4; ++ch) {
            *(uint4*)&As[bf][aoff[ch]] = ar[ch];
            *(uint4*)&Bs[bf][boff[ch]] = wr[ch];
        }
    };

    load_g(0);
    stash(0);
    __syncthreads();

    float acc[4][8][4] = {};

    const int NS = K / 32;   // 12
    int buf = 0;
    for (int s = 0; s < NS; ++s) {
        if (s + 1 < NS) load_g((s + 1) * 32);

#pragma unroll
        for (int kk = 0; kk < 2; ++kk) {
            uint32_t af[4][4], bfr[8][2];
            const uint32_t* Ap = &As[buf][((kk * 8 + warp_m * 4) * 4) * 32 + lane];
            const uint32_t* Bp = &Bs[buf][((kk * 16 + warp_n * 8) * 2) * 32 + lane];
#pragma unroll
            for (int mi = 0; mi < 4; ++mi)
#pragma unroll
                for (int r = 0; r < 4; ++r)
                    af[mi][r] = Ap[(mi * 4 + r) * 32];
#pragma unroll
            for (int ni = 0; ni < 8; ++ni) {
                bfr[ni][0] = Bp[ni * 64];
                bfr[ni][1] = Bp[ni * 64 + 32];
            }
#pragma unroll
            for (int mi = 0; mi < 4; ++mi)
#pragma unroll
                for (int ni = 0; ni < 8; ++ni)
                    mma_f16_k16(acc[mi][ni],
                                af[mi][0], af[mi][1], af[mi][2], af[mi][3],
                                bfr[ni][0], bfr[ni][1]);
        }

        if (s + 1 < NS) {
            stash(buf ^ 1);
            __syncthreads();
            buf ^= 1;
        }
    }

    // epilogue
#pragma unroll
    for (int mi = 0; mi < 4; ++mi) {
#pragma unroll
        for (int ni = 0; ni < 8; ++ni) {
            const int row = bm + warp_m * 64 + mi * 16 + g;
            const int col = bn + warp_n * 64 + ni * 8 + 2 * t;
            const float b0v = __ldg(bias + col);
            const float b1v = __ldg(bias + col + 1);
            const float v00 = acc[mi][ni][0] + b0v, v01 = acc[mi][ni][1] + b1v;
            const float v10 = acc[mi][ni][2] + b0v, v11 = acc[mi][ni][3] + b1v;
            if constexpr (sizeof(TO) == 2) {
                *(__half2*)((__half*)C + (size_t)row * Nout + col) =
                    __floats2half2_rn(v00, v01);
                *(__half2*)((__half*)C + (size_t)(row + 8) * Nout + col) =
                    __floats2half2_rn(v10, v11);
            } else {
                *(float2*)((float*)C + (size_t)row * Nout + col) = make_float2(v00, v01);
                *(float2*)((float*)C + (size_t)(row + 8) * Nout + col) = make_float2(v10, v11);
            }
        }
    }
}

// ---------------------------------------------------------------------------
// Tensor-core attention: one CTA (128 threads, 4 warps) per (window b, head h).
// (unchanged — measured ~130 us, rel_err-verified)
// ---------------------------------------------------------------------------
__global__ __launch_bounds__(128) void attn_mma(const float* __restrict__ mask)
{
    const int b = blockIdx.x;
    const int h = blockIdx.y;
    const int tid  = threadIdx.x;
    const int lane = tid & 31;
    const int w    = tid >> 5;
    const int g = lane >> 2;
    const int t = lane & 3;

    __shared__ __align__(16) __half qh[64][40];
    __shared__ __align__(16) __half kh[64][40];
    __shared__ __align__(16) __half vt[32][72];

    for (int i = tid; i < 64 * 20; i += 128) {
        ((uint32_t*)qh)[i] = 0;
        ((uint32_t*)kh)[i] = 0;
    }
    for (int i = tid; i < 32 * 36; i += 128) ((uint32_t*)vt)[i] = 0;
    __syncthreads();

    const __half* base = g_qkvh + (size_t)(b * NTOK) * THREEC + h * DH;
    for (int idx = tid; idx < NTOK * 16; idx += 128) {
        const int n  = idx >> 4;
        const int d2 = idx & 15;
        const uint32_t* p = (const uint32_t*)(base + (size_t)n * THREEC) + d2;
        const uint32_t q = p[0];
        const uint32_t k = p[CDIM / 2];
        const uint32_t v = p[CDIM];
        *(uint32_t*)&qh[n][d2 * 2] = q;
        *(uint32_t*)&kh[n][d2 * 2] = k;
        const __half2 vh = *(const __half2*)&v;
        vt[d2 * 2][n]     = __low2half(vh);
        vt[d2 * 2 + 1][n] = __high2half(vh);
    }
    __syncthreads();

    const int m0 = w * 16;
    const int r   = lane & 7;
    const int mat = lane >> 3;
    const int lrow = r + (mat & 1) * 8;
    const int lcol = (mat >> 1) * 8;

    uint32_t a[2][4];
#pragma unroll
    for (int s = 0; s < 2; ++s)
        ldsm4(a[s][0], a[s][1], a[s][2], a[s][3],
              smem_u32(&qh[m0 + lrow][lcol + s * 16]));

    float c[7][4] = {};
#pragma unroll
    for (int s = 0; s < 2; ++s) {
#pragma unroll
        for (int p = 0; p < 4; ++p) {
            uint32_t b0, b1, b2, b3;
            ldsm4(b0, b1, b2, b3, smem_u32(&kh[16 * p + lrow][lcol + s * 16]));
            mma_f16_k16(c[2 * p], a[s][0], a[s][1], a[s][2], a[s][3], b0, b2);
            if (2 * p + 1 < 7)
                mma_f16_k16(c[2 * p + 1], a[s][0], a[s][1], a[s][2], a[s][3], b1, b3);
        }
    }

    const float scale = 0.17677669529663687f;
    const float* mrow = mask + (size_t)(b & (NWMASK - 1)) * NTOK * NTOK;
    const int i1 = m0 + g;
    const int i2 = m0 + 8 + g;
    const int mi1 = (i1 < NTOK) ? i1 : NTOK - 1;
    const int mi2 = (i2 < NTOK) ? i2 : NTOK - 1;
#pragma unroll
    for (int nt = 0; nt < 7; ++nt) {
        const int j0 = nt * 8 + 2 * t;
        c[nt][0] = (j0     < NTOK) ? c[nt][0] * scale + __ldg(mrow + mi1 * NTOK + j0)     : -1e30f;
        c[nt][1] = (j0 + 1 < NTOK) ? c[nt][1] * scale + __ldg(mrow + mi1 * NTOK + j0 + 1) : -1e30f;
        c[nt][2] = (j0     < NTOK) ? c[nt][2] * scale + __ldg(mrow + mi2 * NTOK + j0)     : -1e30f;
        c[nt][3] = (j0 + 1 < NTOK) ? c[nt][3] * scale + __ldg(mrow + mi2 * NTOK + j0 + 1) : -1e30f;
    }

    float mx1 = -1e30f, mx2 = -1e30f;
#pragma unroll
    for (int nt = 0; nt < 7; ++nt) {
        mx1 = fmaxf(mx1, fmaxf(c[nt][0], c[nt][1]));
        mx2 = fmaxf(mx2, fmaxf(c[nt][2], c[nt][3]));
    }
    mx1 = fmaxf(mx1, __shfl_xor_sync(0xffffffffu, mx1, 1));
    mx1 = fmaxf(mx1, __shfl_xor_sync(0xffffffffu, mx1, 2));
    mx2 = fmaxf(mx2, __shfl_xor_sync(0xffffffffu, mx2, 1));
    mx2 = fmaxf(mx2, __shfl_xor_sync(0xffffffffu, mx2, 2));

    float s1 = 0.f, s2 = 0.f;
#pragma unroll
    for (int nt = 0; nt < 7; ++nt) {
        c[nt][0] = __expf(c[nt][0] - mx1);
        c[nt][1] = __expf(c[nt][1] - mx1);
        c[nt][2] = __expf(c[nt][2] - mx2);
        c[nt][3] = __expf(c[nt][3] - mx2);
        s1 += c[nt][0] + c[nt][1];
        s2 += c[nt][2] + c[nt][3];
    }
    s1 += __shfl_xor_sync(0xffffffffu, s1, 1);
    s1 += __shfl_xor_sync(0xffffffffu, s1, 2);
    s2 += __shfl_xor_sync(0xffffffffu, s2, 1);
    s2 += __shfl_xor_sync(0xffffffffu, s2, 2);
    const float inv1 = 1.0f / s1;
    const float inv2 = 1.0f / s2;

    uint32_t pa[7][2];
#pragma unroll
    for (int nt = 0; nt < 7; ++nt) {
        const __half2 p0 = __floats2half2_rn(c[nt][0] * inv1, c[nt][1] * inv1);
        const __half2 p1 = __floats2half2_rn(c[nt][2] * inv2, c[nt][3] * inv2);
        pa[nt][0] = *(const uint32_t*)&p0;
        pa[nt][1] = *(const uint32_t*)&p1;
    }

    float o[4][4] = {};
#pragma unroll
    for (int kc = 0; kc < 7; ++kc) {
#pragma unroll
        for (int dt = 0; dt < 4; ++dt) {
            const uint32_t bv = *(const uint32_t*)&vt[dt * 8 + g][kc * 8 + 2 * t];
            mma_f16_k8(o[dt], pa[kc][0], pa[kc][1], bv);
        }
    }

    __half* ob = g_atth + (size_t)(b * NTOK) * CDIM + h * DH;
#pragma unroll
    for (int dt = 0; dt < 4; ++dt) {
        const int d0 = dt * 8 + 2 * t;
        if (i1 < NTOK)
            *(__half2*)(ob + (size_t)i1 * CDIM + d0) = __floats2half2_rn(o[dt][0], o[dt][1]);
        if (i2 < NTOK)
            *(__half2*)(ob + (size_t)i2 * CDIM + d0) = __floats2half2_rn(o[dt][2], o[dt][3]);
    }
}

// ---------------------------------------------------------------------------
// launch
// ---------------------------------------------------------------------------
extern "C" void kernel_launch(void* const* d_in, const int* in_sizes, int n_in,
                              void* d_out, int out_size)
{
    const float* x      = (const float*)d_in[0];
    const float* mask   = (const float*)d_in[1];
    const float* qkv_w  = (const float*)d_in[2];
    const float* qkv_b  = (const float*)d_in[3];
    const float* proj_w = (const float*)d_in[4];
    const float* proj_b = (const float*)d_in[5];
    float* out = (float*)d_out;

    __half *qkvh_ptr, *xh_ptr, *atth_ptr, *wqh_ptr, *wph_ptr;
    cudaGetSymbolAddress((void**)&qkvh_ptr, g_qkvh);
    cudaGetSymbolAddress((void**)&xh_ptr,   g_xh);
    cudaGetSymbolAddress((void**)&atth_ptr, g_atth);
    cudaGetSymbolAddress((void**)&wqh_ptr,  g_wqh);
    cudaGetSymbolAddress((void**)&wph_ptr,  g_wph);

    // 0) fp32 -> fp16 prepass
    {
        const int nx = (MROWS * CDIM) / 8;
        to_half_kernel<<<(nx + 255) / 256, 256>>>(x, xh_ptr, nx);
        const int nq = (THREEC * CDIM) / 8;
        to_half_kernel<<<(nq + 255) / 256, 256>>>(qkv_w, wqh_ptr, nq);
        const int np = (CDIM * CDIM) / 8;
        to_half_kernel<<<(np + 255) / 256, 256>>>(proj_w, wph_ptr, np);
    }
    // 1) QKV GEMM: fp16 in / fp16 out
    {
        dim3 grid(THREEC / 128, MROWS / 128);   // (9, 784)
        gemm_f16_v6<__half><<<grid, 128>>>(xh_ptr, wqh_ptr, qkv_b, qkvh_ptr, THREEC, CDIM);
    }
    // 2) windowed attention (tensor cores, fp16 in/out)
    {
        dim3 grid(BWIN, HHEADS);
        attn_mma<<<grid, 128>>>(mask);
    }
    // 3) Proj GEMM: fp16 in / fp32 out
    {
        dim3 grid(CDIM / 128, MROWS / 128);     // (3, 784)
        gemm_f16_v6<float><<<grid, 128>>>(atth_ptr, wph_ptr, proj_b, out, CDIM, CDIM);
    }
}

// round 11
// speedup vs baseline: 1.1465x; 1.1465x over previous
#include <cuda_runtime.h>
#include <cuda_fp16.h>
#include <cstdint>

// Problem constants (fixed by reference)
#define BWIN   2048
#define NTOK   49
#define CDIM   384
#define HHEADS 12
#define DH     32
#define NWMASK 64
#define THREEC 1152
#define MROWS  (BWIN * NTOK)   // 100352

// Scratch (allocation-free rule: __device__ globals)
__device__ __half g_qkvh[(size_t)MROWS * THREEC];   // qkv, fp16
__device__ __half g_xh  [(size_t)MROWS * CDIM];     // x, fp16
__device__ __half g_atth[(size_t)MROWS * CDIM];     // attention out, fp16
__device__ __half g_wqh [(size_t)THREEC * CDIM];    // qkv_w, fp16
__device__ __half g_wph [(size_t)CDIM * CDIM];      // proj_w, fp16

// ---------------------------------------------------------------------------
// helpers
// ---------------------------------------------------------------------------
__device__ __forceinline__ void mma_f16_k16(float c[4],
                                            uint32_t a0, uint32_t a1, uint32_t a2, uint32_t a3,
                                            uint32_t b0, uint32_t b1) {
    asm volatile(
        "mma.sync.aligned.m16n8k16.row.col.f32.f16.f16.f32 "
        "{%0,%1,%2,%3}, {%4,%5,%6,%7}, {%8,%9}, {%0,%1,%2,%3};"
        : "+f"(c[0]), "+f"(c[1]), "+f"(c[2]), "+f"(c[3])
        : "r"(a0), "r"(a1), "r"(a2), "r"(a3), "r"(b0), "r"(b1));
}

__device__ __forceinline__ void mma_f16_k8(float c[4],
                                           uint32_t a0, uint32_t a1, uint32_t b0) {
    asm volatile(
        "mma.sync.aligned.m16n8k8.row.col.f32.f16.f16.f32 "
        "{%0,%1,%2,%3}, {%4,%5}, {%6}, {%0,%1,%2,%3};"
        : "+f"(c[0]), "+f"(c[1]), "+f"(c[2]), "+f"(c[3])
        : "r"(a0), "r"(a1), "r"(b0));
}

__device__ __forceinline__ void ldsm4(uint32_t& r0, uint32_t& r1,
                                      uint32_t& r2, uint32_t& r3, uint32_t addr) {
    asm volatile("ldmatrix.sync.aligned.m8n8.x4.shared.b16 {%0,%1,%2,%3}, [%4];"
                 : "=r"(r0), "=r"(r1), "=r"(r2), "=r"(r3) : "r"(addr));
}

__device__ __forceinline__ uint32_t smem_u32(const void* p) {
    return (uint32_t)__cvta_generic_to_shared(p);
}

// ---------------------------------------------------------------------------
// prepass: fp32 -> fp16 (rn); 8 floats per thread
// ---------------------------------------------------------------------------
__global__ void to_half_kernel(const float* __restrict__ in,
                               __half* __restrict__ out, int n8)
{
    const int i = blockIdx.x * blockDim.x + threadIdx.x;
    if (i < n8) {
        const float4 v0 = ((const float4*)in)[2 * i];
        const float4 v1 = ((const float4*)in)[2 * i + 1];
        __half2 h[4];
        h[0] = __floats2half2_rn(v0.x, v0.y);
        h[1] = __floats2half2_rn(v0.z, v0.w);
        h[2] = __floats2half2_rn(v1.x, v1.y);
        h[3] = __floats2half2_rn(v1.z, v1.w);
        ((uint4*)out)[i] = *(uint4*)h;
    }
}

// ---------------------------------------------------------------------------
// fp16 tensor-core GEMM v7:  v4's proven config + BK=64 (half the barriers)
// CTA tile 256x128, 256 threads = 8 warps (4m x 2n), warp tile 64x64.
// Stage = 64 halfs of K, built from two 32-wide producer phases (register
// staging capped at 6 uint4). ONE __syncthreads per stage (6 total, K=384).
// Fragment-permuted smem, dense per 64-wide stage:
//   A word idx: ((kks*16 + mi)*4 + (hi+2ph))*32 + g2*4 + t   kks 0..3 (8192 w)
//   B word idx: ((kks*16 + ni)*2 + ph)*32 + gb*4 + t         kks 0..3 (4096 w)
// Dynamic smem: 2*(8192+4096)*4 = 96KB.
// ---------------------------------------------------------------------------
#define AWORDS 8192
#define BWORDS 4096
#define GEMM_SMEM ((AWORDS + BWORDS) * 2 * 4)   // 98304

template <typename TO>
__global__ __launch_bounds__(256, 1) void gemm_f16_v7(
    const __half* __restrict__ A,
    const __half* __restrict__ W,
    const float* __restrict__ bias,
    TO* __restrict__ C,
    int Nout, int K)
{
    extern __shared__ __align__(16) uint32_t dsm[];
    uint32_t* const As = dsm;                     // [2][AWORDS]
    uint32_t* const Bs = dsm + 2 * AWORDS;        // [2][BWORDS]

    const int tid  = threadIdx.x;
    const int bm   = blockIdx.y * 256;
    const int bn   = blockIdx.x * 128;
    const int lane = tid & 31;
    const int warp = tid >> 5;
    const int warp_m = warp >> 1;    // 0..3 (64-row slab)
    const int warp_n = warp & 1;     // 0..1 (64-col slab)
    const int g = lane >> 2;
    const int t = lane & 3;

    // producer: row set {ldr, +64, +128, +192} for A, {ldr, +64} for B;
    // chunk c covers 8 halfs; phase p adds 32 cols (kks += 2).
    const int ldr = tid >> 2;            // 0..63
    const int c   = tid & 3;             // 0..3
    const int kks0 = c >> 1;             // 0..1 (phase-lo kks)
    const int ph   = c & 1;

    const __half* Ab = A + (size_t)(bm + ldr) * K + c * 8;
    const __half* Wb = W + (size_t)(bn + ldr) * K + c * 8;

    // offsets per phase (word units)
    int aoff[2][4], boff[2][2];
#pragma unroll
    for (int p = 0; p < 2; ++p) {
        const int kks = kks0 + p * 2;
#pragma unroll
        for (int i = 0; i < 4; ++i) {
            const int row = ldr + i * 64;
            const int mi  = row >> 4;
            const int lr  = row & 15;
            aoff[p][i] = ((kks * 16 + mi) * 4 + ((lr >> 3) + 2 * ph)) * 32 + (lr & 7) * 4;
        }
#pragma unroll
        for (int i = 0; i < 2; ++i) {
            const int n = ldr + i * 64;
            boff[p][i] = ((kks * 16 + (n >> 3)) * 2 + ph) * 32 + (n & 7) * 4;
        }
    }

    uint4 ar[4], wr[2];

    auto load_ph = [&](int s, int p) {   // stage s, phase p (cols p*32..p*32+31)
        const int k0 = s * 64 + p * 32;
        ar[0] = *(const uint4*)(Ab + k0);
        ar[1] = *(const uint4*)(Ab + (size_t)64  * K + k0);
        ar[2] = *(const uint4*)(Ab + (size_t)128 * K + k0);
        ar[3] = *(const uint4*)(Ab + (size_t)192 * K + k0);
        wr[0] = *(const uint4*)(Wb + k0);
        wr[1] = *(const uint4*)(Wb + (size_t)64  * K + k0);
    };
    auto stash_ph = [&](int bf, int p) {
        uint32_t* Ad = As + bf * AWORDS;
        uint32_t* Bd = Bs + bf * BWORDS;
#pragma unroll
        for (int i = 0; i < 4; ++i) *(uint4*)&Ad[aoff[p][i]] = ar[i];
#pragma unroll
        for (int i = 0; i < 2; ++i) *(uint4*)&Bd[boff[p][i]] = wr[i];
    };

    // consumer for one k16 step kk (0..3) on buffer bf
    float acc[4][8][4] = {};
    auto mma_step = [&](int bf, int kk) {
        uint32_t af[4][4], bfr[8][2];
        const uint32_t* Ap = As + bf * AWORDS + ((kk * 16 + warp_m * 4) * 4) * 32 + lane;
        const uint32_t* Bp = Bs + bf * BWORDS + ((kk * 16 + warp_n * 8) * 2) * 32 + lane;
#pragma unroll
        for (int mi = 0; mi < 4; ++mi)
#pragma unroll
            for (int r = 0; r < 4; ++r)
                af[mi][r] = Ap[(mi * 4 + r) * 32];
#pragma unroll
        for (int ni = 0; ni < 8; ++ni) {
            bfr[ni][0] = Bp[ni * 64];
            bfr[ni][1] = Bp[ni * 64 + 32];
        }
#pragma unroll
        for (int mi = 0; mi < 4; ++mi)
#pragma unroll
            for (int ni = 0; ni < 8; ++ni)
                mma_f16_k16(acc[mi][ni],
                            af[mi][0], af[mi][1], af[mi][2], af[mi][3],
                            bfr[ni][0], bfr[ni][1]);
    };

    // prologue: fill stage 0
    load_ph(0, 0); stash_ph(0, 0);
    load_ph(0, 1); stash_ph(0, 1);
    __syncthreads();

    const int NS = K / 64;   // 6
    int buf = 0;
    for (int s = 0; s < NS; ++s) {
        const bool more = (s + 1 < NS);
        if (more) load_ph(s + 1, 0);
        mma_step(buf, 0);
        mma_step(buf, 1);
        if (more) { stash_ph(buf ^ 1, 0); load_ph(s + 1, 1); }
        mma_step(buf, 2);
        mma_step(buf, 3);
        if (more) {
            stash_ph(buf ^ 1, 1);
            __syncthreads();
            buf ^= 1;
        }
    }

    // epilogue: frag layout m16n8: c0=(g,2t) c1=(g,2t+1) c2=(g+8,2t) c3=(g+8,2t+1)
#pragma unroll
    for (int mi = 0; mi < 4; ++mi) {
#pragma unroll
        for (int ni = 0; ni < 8; ++ni) {
            const int row = bm + warp_m * 64 + mi * 16 + g;
            const int col = bn + warp_n * 64 + ni * 8 + 2 * t;
            const float b0v = __ldg(bias + col);
            const float b1v = __ldg(bias + col + 1);
            const float v00 = acc[mi][ni][0] + b0v, v01 = acc[mi][ni][1] + b1v;
            const float v10 = acc[mi][ni][2] + b0v, v11 = acc[mi][ni][3] + b1v;
            if constexpr (sizeof(TO) == 2) {
                *(__half2*)((__half*)C + (size_t)row * Nout + col) =
                    __floats2half2_rn(v00, v01);
                *(__half2*)((__half*)C + (size_t)(row + 8) * Nout + col) =
                    __floats2half2_rn(v10, v11);
            } else {
                *(float2*)((float*)C + (size_t)row * Nout + col) = make_float2(v00, v01);
                *(float2*)((float*)C + (size_t)(row + 8) * Nout + col) = make_float2(v10, v11);
            }
        }
    }
}

// ---------------------------------------------------------------------------
// Tensor-core attention: one CTA (128 threads, 4 warps) per (window b, head h).
// (unchanged — measured ~130 us, rel_err-verified)
// ---------------------------------------------------------------------------
__global__ __launch_bounds__(128) void attn_mma(const float* __restrict__ mask)
{
    const int b = blockIdx.x;
    const int h = blockIdx.y;
    const int tid  = threadIdx.x;
    const int lane = tid & 31;
    const int w    = tid >> 5;
    const int g = lane >> 2;
    const int t = lane & 3;

    __shared__ __align__(16) __half qh[64][40];
    __shared__ __align__(16) __half kh[64][40];
    __shared__ __align__(16) __half vt[32][72];

    for (int i = tid; i < 64 * 20; i += 128) {
        ((uint32_t*)qh)[i] = 0;
        ((uint32_t*)kh)[i] = 0;
    }
    for (int i = tid; i < 32 * 36; i += 128) ((uint32_t*)vt)[i] = 0;
    __syncthreads();

    const __half* base = g_qkvh + (size_t)(b * NTOK) * THREEC + h * DH;
    for (int idx = tid; idx < NTOK * 16; idx += 128) {
        const int n  = idx >> 4;
        const int d2 = idx & 15;
        const uint32_t* p = (const uint32_t*)(base + (size_t)n * THREEC) + d2;
        const uint32_t q = p[0];
        const uint32_t k = p[CDIM / 2];
        const uint32_t v = p[CDIM];
        *(uint32_t*)&qh[n][d2 * 2] = q;
        *(uint32_t*)&kh[n][d2 * 2] = k;
        const __half2 vh = *(const __half2*)&v;
        vt[d2 * 2][n]     = __low2half(vh);
        vt[d2 * 2 + 1][n] = __high2half(vh);
    }
    __syncthreads();

    const int m0 = w * 16;
    const int r   = lane & 7;
    const int mat = lane >> 3;
    const int lrow = r + (mat & 1) * 8;
    const int lcol = (mat >> 1) * 8;

    uint32_t a[2][4];
#pragma unroll
    for (int s = 0; s < 2; ++s)
        ldsm4(a[s][0], a[s][1], a[s][2], a[s][3],
              smem_u32(&qh[m0 + lrow][lcol + s * 16]));

    float c[7][4] = {};
#pragma unroll
    for (int s = 0; s < 2; ++s) {
#pragma unroll
        for (int p = 0; p < 4; ++p) {
            uint32_t b0, b1, b2, b3;
            ldsm4(b0, b1, b2, b3, smem_u32(&kh[16 * p + lrow][lcol + s * 16]));
            mma_f16_k16(c[2 * p], a[s][0], a[s][1], a[s][2], a[s][3], b0, b2);
            if (2 * p + 1 < 7)
                mma_f16_k16(c[2 * p + 1], a[s][0], a[s][1], a[s][2], a[s][3], b1, b3);
        }
    }

    const float scale = 0.17677669529663687f;
    const float* mrow = mask + (size_t)(b & (NWMASK - 1)) * NTOK * NTOK;
    const int i1 = m0 + g;
    const int i2 = m0 + 8 + g;
    const int mi1 = (i1 < NTOK) ? i1 : NTOK - 1;
    const int mi2 = (i2 < NTOK) ? i2 : NTOK - 1;
#pragma unroll
    for (int nt = 0; nt < 7; ++nt) {
        const int j0 = nt * 8 + 2 * t;
        c[nt][0] = (j0     < NTOK) ? c[nt][0] * scale + __ldg(mrow + mi1 * NTOK + j0)     : -1e30f;
        c[nt][1] = (j0 + 1 < NTOK) ? c[nt][1] * scale + __ldg(mrow + mi1 * NTOK + j0 + 1) : -1e30f;
        c[nt][2] = (j0     < NTOK) ? c[nt][2] * scale + __ldg(mrow + mi2 * NTOK + j0)     : -1e30f;
        c[nt][3] = (j0 + 1 < NTOK) ? c[nt][3] * scale + __ldg(mrow + mi2 * NTOK + j0 + 1) : -1e30f;
    }

    float mx1 = -1e30f, mx2 = -1e30f;
#pragma unroll
    for (int nt = 0; nt < 7; ++nt) {
        mx1 = fmaxf(mx1, fmaxf(c[nt][0], c[nt][1]));
        mx2 = fmaxf(mx2, fmaxf(c[nt][2], c[nt][3]));
    }
    mx1 = fmaxf(mx1, __shfl_xor_sync(0xffffffffu, mx1, 1));
    mx1 = fmaxf(mx1, __shfl_xor_sync(0xffffffffu, mx1, 2));
    mx2 = fmaxf(mx2, __shfl_xor_sync(0xffffffffu, mx2, 1));
    mx2 = fmaxf(mx2, __shfl_xor_sync(0xffffffffu, mx2, 2));

    float s1 = 0.f, s2 = 0.f;
#pragma unroll
    for (int nt = 0; nt < 7; ++nt) {
        c[nt][0] = __expf(c[nt][0] - mx1);
        c[nt][1] = __expf(c[nt][1] - mx1);
        c[nt][2] = __expf(c[nt][2] - mx2);
        c[nt][3] = __expf(c[nt][3] - mx2);
        s1 += c[nt][0] + c[nt][1];
        s2 += c[nt][2] + c[nt][3];
    }
    s1 += __shfl_xor_sync(0xffffffffu, s1, 1);
    s1 += __shfl_xor_sync(0xffffffffu, s1, 2);
    s2 += __shfl_xor_sync(0xffffffffu, s2, 1);
    s2 += __shfl_xor_sync(0xffffffffu, s2, 2);
    const float inv1 = 1.0f / s1;
    const float inv2 = 1.0f / s2;

    uint32_t pa[7][2];
#pragma unroll
    for (int nt = 0; nt < 7; ++nt) {
        const __half2 p0 = __floats2half2_rn(c[nt][0] * inv1, c[nt][1] * inv1);
        const __half2 p1 = __floats2half2_rn(c[nt][2] * inv2, c[nt][3] * inv2);
        pa[nt][0] = *(const uint32_t*)&p0;
        pa[nt][1] = *(const uint32_t*)&p1;
    }

    float o[4][4] = {};
#pragma unroll
    for (int kc = 0; kc < 7; ++kc) {
#pragma unroll
        for (int dt = 0; dt < 4; ++dt) {
            const uint32_t bv = *(const uint32_t*)&vt[dt * 8 + g][kc * 8 + 2 * t];
            mma_f16_k8(o[dt], pa[kc][0], pa[kc][1], bv);
        }
    }

    __half* ob = g_atth + (size_t)(b * NTOK) * CDIM + h * DH;
#pragma unroll
    for (int dt = 0; dt < 4; ++dt) {
        const int d0 = dt * 8 + 2 * t;
        if (i1 < NTOK)
            *(__half2*)(ob + (size_t)i1 * CDIM + d0) = __floats2half2_rn(o[dt][0], o[dt][1]);
        if (i2 < NTOK)
            *(__half2*)(ob + (size_t)i2 * CDIM + d0) = __floats2half2_rn(o[dt][2], o[dt][3]);
    }
}

// ---------------------------------------------------------------------------
// launch
// ---------------------------------------------------------------------------
extern "C" void kernel_launch(void* const* d_in, const int* in_sizes, int n_in,
                              void* d_out, int out_size)
{
    const float* x      = (const float*)d_in[0];
    const float* mask   = (const float*)d_in[1];
    const float* qkv_w  = (const float*)d_in[2];
    const float* qkv_b  = (const float*)d_in[3];
    const float* proj_w = (const float*)d_in[4];
    const float* proj_b = (const float*)d_in[5];
    float* out = (float*)d_out;

    __half *qkvh_ptr, *xh_ptr, *atth_ptr, *wqh_ptr, *wph_ptr;
    cudaGetSymbolAddress((void**)&qkvh_ptr, g_qkvh);
    cudaGetSymbolAddress((void**)&xh_ptr,   g_xh);
    cudaGetSymbolAddress((void**)&atth_ptr, g_atth);
    cudaGetSymbolAddress((void**)&wqh_ptr,  g_wqh);
    cudaGetSymbolAddress((void**)&wph_ptr,  g_wph);

    cudaFuncSetAttribute(gemm_f16_v7<__half>,
                         cudaFuncAttributeMaxDynamicSharedMemorySize, GEMM_SMEM);
    cudaFuncSetAttribute(gemm_f16_v7<float>,
                         cudaFuncAttributeMaxDynamicSharedMemorySize, GEMM_SMEM);

    // 0) fp32 -> fp16 prepass
    {
        const int nx = (MROWS * CDIM) / 8;
        to_half_kernel<<<(nx + 255) / 256, 256>>>(x, xh_ptr, nx);
        const int nq = (THREEC * CDIM) / 8;
        to_half_kernel<<<(nq + 255) / 256, 256>>>(qkv_w, wqh_ptr, nq);
        const int np = (CDIM * CDIM) / 8;
        to_half_kernel<<<(np + 255) / 256, 256>>>(proj_w, wph_ptr, np);
    }
    // 1) QKV GEMM: fp16 in / fp16 out
    {
        dim3 grid(THREEC / 128, MROWS / 256);   // (9, 392)
        gemm_f16_v7<__half><<<grid, 256, GEMM_SMEM>>>(xh_ptr, wqh_ptr, qkv_b,
                                                      qkvh_ptr, THREEC, CDIM);
    }
    // 2) windowed attention (tensor cores, fp16 in/out)
    {
        dim3 grid(BWIN, HHEADS);
        attn_mma<<<grid, 128>>>(mask);
    }
    // 3) Proj GEMM: fp16 in / fp32 out
    {
        dim3 grid(CDIM / 128, MROWS / 256);     // (3, 392)
        gemm_f16_v7<float><<<grid, 256, GEMM_SMEM>>>(atth_ptr, wph_ptr, proj_b,
                                                     out, CDIM, CDIM);
    }
}